// round 13
// baseline (speedup 1.0000x reference)
#include <cuda_runtime.h>

#define NTHR 512
#define TPG  16            // tokens per group
#define S    276           // staging row stride in floats (16*16 + 20 pad)

typedef unsigned long long ull;

// ---------------- shared memory layout (in floats) ----------------
#define WBT_SZ  (9*32*64)              // wbT[a][i][o], o contiguous
#define WOT_SZ  (9*32*32)              // woT[a][i][o]
#define XS_SZ   (32*S + 8)             // xs rows (aliased by gs in P3/P4)
#define HS_SZ   (64*S + 8)             // hs rows (aliased by out-staging)
#define WBT_OFF 0
#define WOT_OFF (WBT_OFF + WBT_SZ)
#define XS_OFF  (WOT_OFF + WOT_SZ)
#define HS_OFF  (XS_OFF + XS_SZ)
#define BB_OFF  (HS_OFF + HS_SZ)       // 64
#define BO_OFF  (BB_OFF + 64)          // 32
#define RW_OFF  (BO_OFF + 32)          // 16
#define F_TOTAL (RW_OFF + 16)
#define SMEM_BYTES (F_TOTAL * 4)

// component slot swizzle (bijective), bank-swizzled row offsets
__host__ __device__ constexpr int cslot(int k) { return k ^ (k >> 2); }
__host__ __device__ constexpr int rowX(int i)  { return XS_OFF + i * S + ((i >> 3) & 1) * 4; }
__host__ __device__ constexpr int rowH(int o)  { return HS_OFF + o * S + ((o >> 3) & 1) * 4; }

// ---------------- blade algebra ----------------
// blade order: 1,e0,e1,e2,e3,e01,e02,e03,e12,e13,e23,e012,e013,e023,e123,e0123
__constant__ int c_GRADE[16] = {0,1,1,1,1,2,2,2,2,2,2,3,3,3,3,4};
__constant__ int c_PART [16] = {-1,0,-1,-1,-1,2,3,4,-1,-1,-1,8,9,10,-1,14};
__constant__ int c_A2   [16] = {0,5,0,0,0,6,6,6,0,0,0,7,7,7,0,8};
// warp -> component; EK/NK interleaved in groups of 4 so each SMSP gets 2+2
__constant__ int c_KORD [16] = {1,5,6,7, 0,2,3,4, 11,12,13,15, 8,9,10,14};

// ---- compile-time Cayley tables ----
constexpr int MASKC[16]  = {0,1,2,4,8,3,5,9,6,10,12,7,11,13,14,15};
constexpr int IMASKC[16] = {0,1,2,5,3,6,8,11,4,7,9,12,10,13,14,15};
constexpr int popc4c(int x) { int v = 0; for (int b = 0; b < 4; b++) v += (x >> b) & 1; return v; }
constexpr int invcc(int A, int B) {
    int v = 0;
    for (int g = 0; g < 4; g++) if ((B >> g) & 1) v += popc4c(A >> (g + 1));
    return v;
}
struct CTerm { int i, j, s; };
struct CK    { CTerm t[16]; int n; };
struct CTabs { CK gp[16]; CK jc[16]; };
constexpr CTabs buildT() {
    CTabs T{};
    for (int i = 0; i < 16; i++)
        for (int j = 0; j < 16; j++) {
            int A = MASKC[i], B = MASKC[j];
            if (A & B & 1) continue;                    // e0*e0 = 0
            int s = (invcc(A, B) & 1) ? -1 : 1;
            int k = IMASKC[A ^ B];
            T.gp[k].t[T.gp[k].n].i = i;
            T.gp[k].t[T.gp[k].n].j = j;
            T.gp[k].t[T.gp[k].n].s = s;
            T.gp[k].n++;
        }
    int ds[16] = {};
    for (int i = 0; i < 16; i++) {
        int A = MASKC[i];
        ds[i] = (invcc(A, 15 ^ A) & 1) ? -1 : 1;
    }
    for (int i = 0; i < 16; i++)
        for (int j = 0; j < 16; j++) {
            int A = MASKC[i], B = MASKC[j];
            int da = 15 ^ A, db = 15 ^ B;
            if (da & db) continue;                      // wedge of duals vanishes
            int w  = (invcc(da, db) & 1) ? -1 : 1;
            int kk = IMASKC[A & B];
            int val = ds[i] * ds[j] * w * ds[kk];
            T.jc[kk].t[T.jc[kk].n].i = i;
            T.jc[kk].t[T.jc[kk].n].j = j;
            T.jc[kk].t[T.jc[kk].n].s = val;
            T.jc[kk].n++;
        }
    return T;
}
constexpr CTabs CT = buildT();

// ---- packed f32x2 helpers ----
__device__ __forceinline__ void fma2(ull& d, ull a, ull b) {
    asm("fma.rn.f32x2 %0, %1, %2, %0;" : "+l"(d) : "l"(a), "l"(b));
}
__device__ __forceinline__ ull pk2(float s) {
    ull d; asm("mov.b64 %0, {%1, %1};" : "=l"(d) : "f"(s)); return d;
}
__device__ __forceinline__ void add2(ull& d, ull a) {
    asm("add.rn.f32x2 %0, %0, %1;" : "+l"(d) : "l"(a));
}

// ---- P2 equi_linear: component k, o-pair (o0,o0+1), 16 tokens (uniform x) ----
// EK components: single fused loop over both weight tables.
__device__ __forceinline__ void el16(
    int k, int o0, const float* __restrict__ wT,
    const float* __restrict__ smb, const float* __restrict__ bias,
    float* __restrict__ dsm)
{
    ull aA[8], aB[8];
    #pragma unroll
    for (int q = 0; q < 8; q++) { aA[q] = 0ull; aB[q] = 0ull; }

    const int g  = c_GRADE[k];
    const int sl = cslot(k) * 16;
    const int pk = c_PART[k];
    const float* w1 = wT + (g * 32) * 64 + o0;

    if (pk >= 0) {
        const int sl2 = cslot(pk) * 16;
        const float* w2 = wT + (c_A2[k] * 32) * 64 + o0;
        #pragma unroll 4
        for (int i = 0; i < 32; i++) {
            float2 wv1 = *(const float2*)(w1 + i * 64);
            float2 wv2 = *(const float2*)(w2 + i * 64);
            ull wa1 = pk2(wv1.x), wb1 = pk2(wv1.y);
            ull wa2 = pk2(wv2.x), wb2 = pk2(wv2.y);
            const float* xp1 = smb + rowX(i) + sl;
            const float* xp2 = smb + rowX(i) + sl2;
            ulonglong2 u0 = *(const ulonglong2*)(xp1);
            ulonglong2 u1 = *(const ulonglong2*)(xp1 + 4);
            ulonglong2 u2 = *(const ulonglong2*)(xp1 + 8);
            ulonglong2 u3 = *(const ulonglong2*)(xp1 + 12);
            ulonglong2 v0 = *(const ulonglong2*)(xp2);
            ulonglong2 v1 = *(const ulonglong2*)(xp2 + 4);
            ulonglong2 v2 = *(const ulonglong2*)(xp2 + 8);
            ulonglong2 v3 = *(const ulonglong2*)(xp2 + 12);
            ull x1[8] = {u0.x, u0.y, u1.x, u1.y, u2.x, u2.y, u3.x, u3.y};
            ull x2[8] = {v0.x, v0.y, v1.x, v1.y, v2.x, v2.y, v3.x, v3.y};
            #pragma unroll
            for (int p = 0; p < 8; p++) {
                fma2(aA[p], x1[p], wa1); fma2(aB[p], x1[p], wb1);
                fma2(aA[p], x2[p], wa2); fma2(aB[p], x2[p], wb2);
            }
        }
    } else {
        #pragma unroll 8
        for (int i = 0; i < 32; i++) {
            float2 wv = *(const float2*)(w1 + i * 64);
            ull wa = pk2(wv.x), wb = pk2(wv.y);
            const float* xp = smb + rowX(i) + sl;
            ulonglong2 u0 = *(const ulonglong2*)(xp);
            ulonglong2 u1 = *(const ulonglong2*)(xp + 4);
            ulonglong2 u2 = *(const ulonglong2*)(xp + 8);
            ulonglong2 u3 = *(const ulonglong2*)(xp + 12);
            ull xv[8] = {u0.x, u0.y, u1.x, u1.y, u2.x, u2.y, u3.x, u3.y};
            #pragma unroll
            for (int p = 0; p < 8; p++) { fma2(aA[p], xv[p], wa); fma2(aB[p], xv[p], wb); }
        }
    }

    if (k == 0) {
        ull bA = pk2(bias[o0]), bB = pk2(bias[o0 + 1]);
        #pragma unroll
        for (int q = 0; q < 8; q++) { add2(aA[q], bA); add2(aB[q], bB); }
    }
    float* pA = dsm + rowH(o0) + sl;
    float* pB = dsm + rowH(o0 + 1) + sl;
    *(ulonglong2*)(pA)      = make_ulonglong2(aA[0], aA[1]);
    *(ulonglong2*)(pA + 4)  = make_ulonglong2(aA[2], aA[3]);
    *(ulonglong2*)(pA + 8)  = make_ulonglong2(aA[4], aA[5]);
    *(ulonglong2*)(pA + 12) = make_ulonglong2(aA[6], aA[7]);
    *(ulonglong2*)(pB)      = make_ulonglong2(aB[0], aB[1]);
    *(ulonglong2*)(pB + 4)  = make_ulonglong2(aB[2], aB[3]);
    *(ulonglong2*)(pB + 8)  = make_ulonglong2(aB[4], aB[5]);
    *(ulonglong2*)(pB + 12) = make_ulonglong2(aB[6], aB[7]);
}

// ---- P4 equi_linear: component k, o-quad, token-quarter (4 tok), fused EK ----
__device__ __forceinline__ void el4q(
    int k, int o0, int h, const float* __restrict__ wT,
    const float* __restrict__ smb, const float* __restrict__ bias,
    float* __restrict__ dsm)
{
    ull acc[4][2];
    #pragma unroll
    for (int oo = 0; oo < 4; oo++) { acc[oo][0] = 0ull; acc[oo][1] = 0ull; }

    const int g  = c_GRADE[k];
    const int sl = cslot(k) * 16 + h * 4;
    const int pk = c_PART[k];
    const float* w1 = wT + (g * 32) * 32 + o0;

    if (pk >= 0) {
        const int sl2 = cslot(pk) * 16 + h * 4;
        const float* w2 = wT + (c_A2[k] * 32) * 32 + o0;
        #pragma unroll 8
        for (int i = 0; i < 32; i++) {
            float4 wv1 = *(const float4*)(w1 + i * 32);
            float4 wv2 = *(const float4*)(w2 + i * 32);
            ulonglong2 u = *(const ulonglong2*)(smb + rowX(i) + sl);
            ulonglong2 v = *(const ulonglong2*)(smb + rowX(i) + sl2);
            ull w10 = pk2(wv1.x), w11 = pk2(wv1.y), w12 = pk2(wv1.z), w13 = pk2(wv1.w);
            ull w20 = pk2(wv2.x), w21 = pk2(wv2.y), w22 = pk2(wv2.z), w23 = pk2(wv2.w);
            fma2(acc[0][0], u.x, w10); fma2(acc[0][1], u.y, w10);
            fma2(acc[1][0], u.x, w11); fma2(acc[1][1], u.y, w11);
            fma2(acc[2][0], u.x, w12); fma2(acc[2][1], u.y, w12);
            fma2(acc[3][0], u.x, w13); fma2(acc[3][1], u.y, w13);
            fma2(acc[0][0], v.x, w20); fma2(acc[0][1], v.y, w20);
            fma2(acc[1][0], v.x, w21); fma2(acc[1][1], v.y, w21);
            fma2(acc[2][0], v.x, w22); fma2(acc[2][1], v.y, w22);
            fma2(acc[3][0], v.x, w23); fma2(acc[3][1], v.y, w23);
        }
    } else {
        #pragma unroll 8
        for (int i = 0; i < 32; i++) {
            float4 wv = *(const float4*)(w1 + i * 32);
            ulonglong2 u = *(const ulonglong2*)(smb + rowX(i) + sl);
            ull w0 = pk2(wv.x), w1r = pk2(wv.y), w2r = pk2(wv.z), w3r = pk2(wv.w);
            fma2(acc[0][0], u.x, w0);  fma2(acc[0][1], u.y, w0);
            fma2(acc[1][0], u.x, w1r); fma2(acc[1][1], u.y, w1r);
            fma2(acc[2][0], u.x, w2r); fma2(acc[2][1], u.y, w2r);
            fma2(acc[3][0], u.x, w3r); fma2(acc[3][1], u.y, w3r);
        }
    }

    if (k == 0) {
        #pragma unroll
        for (int oo = 0; oo < 4; oo++) {
            ull b = pk2(bias[o0 + oo]);
            add2(acc[oo][0], b); add2(acc[oo][1], b);
        }
    }
    #pragma unroll
    for (int oo = 0; oo < 4; oo++) {
        float* d = dsm + rowH(o0 + oo) + sl;
        *(ulonglong2*)(d) = make_ulonglong2(acc[oo][0], acc[oo][1]);
    }
}

// ---- P3: one component K, compile-time term list ----
template<int SIDE, int K>
__device__ __forceinline__ float bil_k(const float (&L)[16], const float (&R)[16]) {
    constexpr CK ck = SIDE ? CT.jc[K] : CT.gp[K];
    float acc = 0.f;
    #pragma unroll
    for (int e = 0; e < ck.n; e++) {
        float l = (ck.t[e].s < 0) ? -L[ck.t[e].i] : L[ck.t[e].i];
        acc = fmaf(l, R[ck.t[e].j], acc);
    }
    return acc;
}

template<int SIDE, int K>
__device__ __forceinline__ void bil_all(const float (&L)[16], const float (&R)[16],
                                        float* __restrict__ dst, float scale) {
    if constexpr (K < 16) {
        float v = bil_k<SIDE, K>(L, R);
        if constexpr (SIDE) v *= scale;
        dst[cslot(K) * 16] = v;
        bil_all<SIDE, K + 1>(L, R, dst, scale);
    }
}

__global__ __launch_bounds__(NTHR, 1)
void gatr_fused_kernel(
    const float* __restrict__ x, const float* __restrict__ ref,
    const float* __restrict__ w_bil, const float* __restrict__ b_bil,
    const float* __restrict__ w_out, const float* __restrict__ b_out,
    float* __restrict__ out, int ngroups)
{
    extern __shared__ float sm[];
    float* wbT = sm + WBT_OFF;
    float* woT = sm + WOT_OFF;
    float* bb  = sm + BB_OFF;
    float* bo  = sm + BO_OFF;
    float* rw  = sm + RW_OFF;

    const int tid = threadIdx.x;

    // ---- stage weights transposed ----
    for (int e = tid; e < 64 * 32 * 9; e += NTHR) {
        int o = e / 288, r = e % 288, i = r / 9, a = r % 9;
        wbT[(a * 32 + i) * 64 + o] = w_bil[e];
    }
    for (int e = tid; e < 32 * 32 * 9; e += NTHR) {
        int o = e / 288, r = e % 288, i = r / 9, a = r % 9;
        woT[(a * 32 + i) * 32 + o] = w_out[e];
    }
    if (tid < 64) bb[tid] = b_bil[tid];
    if (tid < 32) bo[tid] = b_out[tid];

    const int e_id = tid & 127;
    const int t0   = (tid >> 7) * 4;

    // ---- prefetch + stage first group ----
    float4 pf[4];
    float  prw = 0.f;
    {
        int g = blockIdx.x;
        size_t base = ((size_t)g * TPG + t0) * 512 + (size_t)e_id * 4;
        #pragma unroll
        for (int j = 0; j < 4; j++) pf[j] = *(const float4*)(x + base + (size_t)j * 512);
        if (tid < TPG) prw = ref[((size_t)g * TPG + tid) * 16 + 15];

        const float* p0 = (const float*)&pf[0];
        const float* p1 = (const float*)&pf[1];
        const float* p2 = (const float*)&pf[2];
        const float* p3 = (const float*)&pf[3];
        #pragma unroll
        for (int c = 0; c < 4; c++) {
            int k = (e_id & 3) * 4 + c;
            float* d = sm + rowX(e_id >> 2) + cslot(k) * 16 + t0;
            *(float4*)d = make_float4(p0[c], p1[c], p2[c], p3[c]);
        }
        if (tid < TPG) rw[tid] = prw;
    }

    const int w_id = tid >> 5, lane = tid & 31;
    const int k_my = c_KORD[w_id];

    for (int g = blockIdx.x; g < ngroups; g += gridDim.x) {
        __syncthreads();   // xs / rw ready

        // prefetch next group (LDG latency hidden under P2)
        int gn = g + gridDim.x;
        bool more = gn < ngroups;
        if (more) {
            size_t base = ((size_t)gn * TPG + t0) * 512 + (size_t)e_id * 4;
            #pragma unroll
            for (int j = 0; j < 4; j++) pf[j] = *(const float4*)(x + base + (size_t)j * 512);
            if (tid < TPG) prw = ref[((size_t)gn * TPG + tid) * 16 + 15];
        }

        // ---- P2: equi_linear #1 -> hs rows 0..63 (warp = component, o-pair) ----
        el16(k_my, 2 * lane, wbT, sm, bb, sm);
        __syncthreads();

        // ---- P3: GP + join -> gs (xs region) rows 0..31 (512 threads) ----
        {
            int side = tid >> 8, c = (tid >> 4) & 15, t = tid & 15;
            const float* Lp = sm + rowH(side * 32 + c) + t;
            const float* Rp = sm + rowH(side * 32 + 16 + c) + t;
            float L[16], R[16];
            #pragma unroll
            for (int i = 0; i < 16; i++) {
                L[i] = Lp[cslot(i) * 16];
                R[i] = Rp[cslot(i) * 16];
            }
            float* dst = sm + rowX(side * 16 + c) + t;
            float scale = rw[t];
            if (side == 0) bil_all<0, 0>(L, R, dst, scale);
            else           bil_all<1, 0>(L, R, dst, scale);
        }
        __syncthreads();

        // ---- P4: equi_linear #2 -> staging in hs rows 0..31 ----
        // warp = component; lane = token-quarter(4) x o-quad(8)
        el4q(k_my, 4 * (lane & 7), lane >> 3, woT, sm, bo, sm);
        __syncthreads();

        // ---- P5: coalesced store + stage next group's x ----
        {
            float4 sv[4];
            #pragma unroll
            for (int c = 0; c < 4; c++) {
                int k = (e_id & 3) * 4 + c;
                sv[c] = *(const float4*)(sm + rowH(e_id >> 2) + cslot(k) * 16 + t0);
            }
            size_t base = ((size_t)g * TPG + t0) * 512 + (size_t)e_id * 4;
            const float* s0 = (const float*)&sv[0];
            const float* s1 = (const float*)&sv[1];
            const float* s2 = (const float*)&sv[2];
            const float* s3 = (const float*)&sv[3];
            #pragma unroll
            for (int j = 0; j < 4; j++)
                *(float4*)(out + base + (size_t)j * 512) =
                    make_float4(s0[j], s1[j], s2[j], s3[j]);

            if (more) {
                const float* p0 = (const float*)&pf[0];
                const float* p1 = (const float*)&pf[1];
                const float* p2 = (const float*)&pf[2];
                const float* p3 = (const float*)&pf[3];
                #pragma unroll
                for (int c = 0; c < 4; c++) {
                    int k = (e_id & 3) * 4 + c;
                    float* d = sm + rowX(e_id >> 2) + cslot(k) * 16 + t0;
                    *(float4*)d = make_float4(p0[c], p1[c], p2[c], p3[c]);
                }
                if (tid < TPG) rw[tid] = prw;
            }
        }
    }
}

extern "C" void kernel_launch(void* const* d_in, const int* in_sizes, int n_in,
                              void* d_out, int out_size)
{
    const float* x     = (const float*)d_in[0];
    const float* ref   = (const float*)d_in[1];
    const float* w_bil = (const float*)d_in[2];
    const float* b_bil = (const float*)d_in[3];
    const float* w_out = (const float*)d_in[4];
    const float* b_out = (const float*)d_in[5];
    float* out = (float*)d_out;

    int ntok    = in_sizes[0] / 512;   // 32 channels * 16 components
    int ngroups = ntok / TPG;

    cudaFuncSetAttribute(gatr_fused_kernel,
                         cudaFuncAttributeMaxDynamicSharedMemorySize, SMEM_BYTES);
    gatr_fused_kernel<<<152, NTHR, SMEM_BYTES>>>(x, ref, w_bil, b_bil, w_out, b_out,
                                                 out, ngroups);
}